// round 17
// baseline (speedup 1.0000x reference)
#include <cuda_runtime.h>
#include <cstddef>

#define HH 51
#define NT 224       // 7 warps; warp w owns units j=8w..8w+7, lane = cls*8 + (j&7)
#define BT 8         // batches per block
#define GRID 256
#define TT 512
#define BB 2048
#define TCH 64
#define HSTR 12      // h row stride in floats (48B: 16B-aligned, conflict-free STS)

// dynamic smem layout (floats)
#define OFF_WI 0                        // [51][224] sc*Wih2, keyed by tid
#define OFF_WH (51*224)                 // [51][224] sc*Whh2
#define OFF_H1 (2*51*224)               // [2][52*HSTR] ping-pong
#define OFF_H2 (OFF_H1 + 2*52*HSTR)
#define OFF_XS (OFF_H2 + 2*52*HSTR)     // [64][8]
#define OFF_FC (OFF_XS + TCH*BT)
#define SMF    (OFF_FC + 64)

typedef unsigned long long u64;

__device__ __forceinline__ u64 pack2(float lo, float hi) {
    u64 r; asm("mov.b64 %0, {%1,%2};" : "=l"(r) : "f"(lo), "f"(hi)); return r;
}
__device__ __forceinline__ void unpack2(u64 v, float& lo, float& hi) {
    asm("mov.b64 {%0,%1}, %2;" : "=f"(lo), "=f"(hi) : "l"(v));
}
__device__ __forceinline__ u64 fma2(u64 a, u64 b, u64 c) {
    u64 d; asm("fma.rn.f32x2 %0, %1, %2, %3;" : "=l"(d) : "l"(a), "l"(b), "l"(c)); return d;
}
// v PRE-SCALED by log2 const (weights folded). act = a*rcp(1+ex2(v)) + d
__device__ __forceinline__ float actf2(float v, float a, float d) {
    float e; asm("ex2.approx.ftz.f32 %0, %1;" : "=f"(e) : "f"(v));
    float r; asm("rcp.approx.ftz.f32 %0, %1;" : "=f"(r) : "f"(1.f + e));
    return fmaf(a, r, d);
}
#define C_SIG (-1.442695041f)
#define C_TNH ( 2.885390082f)
__device__ __forceinline__ float tanh_c(float v) {
    float e; asm("ex2.approx.ftz.f32 %0, %1;" : "=f"(e) : "f"(v * C_TNH));
    float r; asm("rcp.approx.ftz.f32 %0, %1;" : "=f"(r) : "f"(1.f + e));
    return fmaf(-2.f, r, 1.f);
}

// BT=8 variant: quarters are 2 batches wide. Transpose gate x batch in-warp,
// update cell state (regs), write h row (float2).
__device__ __forceinline__ void gates_update8(
    u64 acc[4], float a0, float d0, int bit0, int bit1,
    float (&cst)[2], float* __restrict__ hw, int j, bool jv)
{
    float s[8];
#pragma unroll
    for (int i = 0; i < 4; ++i) unpack2(acc[i], s[2*i], s[2*i+1]);
#pragma unroll
    for (int i = 0; i < 8; ++i) s[i] = actf2(s[i], a0, d0);

    // round 1 (xor 8): keep quarters q&1==bit0, exchange the others
    float a1[4];
    {
        const int qx0 = bit0 ? 0 : 1, qx1 = bit0 ? 2 : 3;
        const int qk0 = bit0 ? 1 : 0, qk1 = bit0 ? 3 : 2;
        float ex[4];
        ex[0] = s[qx0*2]; ex[1] = s[qx0*2+1];
        ex[2] = s[qx1*2]; ex[3] = s[qx1*2+1];
#pragma unroll
        for (int i = 0; i < 4; ++i) a1[i] = __shfl_xor_sync(0xFFFFFFFFu, ex[i], 8);
        float k0[4];
        k0[0] = s[qk0*2]; k0[1] = s[qk0*2+1];
        k0[2] = s[qk1*2]; k0[3] = s[qk1*2+1];
#pragma unroll
        for (int i = 0; i < 4; ++i) s[i] = k0[i];
    }
    // round 2 (xor 16): keep quarter with q>>1==bit1
    float r0[2], r1[2];
    {
        float ex[4];
        ex[0] = bit1 ? s[0]  : s[2];
        ex[1] = bit1 ? s[1]  : s[3];
        ex[2] = bit1 ? a1[0] : a1[2];
        ex[3] = bit1 ? a1[1] : a1[3];
#pragma unroll
        for (int i = 0; i < 4; ++i) ex[i] = __shfl_xor_sync(0xFFFFFFFFu, ex[i], 16);
        r0[0] = ex[0]; r0[1] = ex[1];
        r1[0] = ex[2]; r1[1] = ex[3];
        s[0]  = bit1 ? s[2]  : s[0];
        s[1]  = bit1 ? s[3]  : s[1];
        a1[0] = bit1 ? a1[2] : a1[0];
        a1[1] = bit1 ? a1[3] : a1[1];
    }
    float2 hv; float* hp = &hv.x;
#pragma unroll
    for (int i = 0; i < 2; ++i) {
        float iv = bit1 ? (bit0 ? r1[i] : r0[i]) : (bit0 ? a1[i] : s[i]);
        float fv = bit1 ? (bit0 ? r0[i] : r1[i]) : (bit0 ? s[i]  : a1[i]);
        float gv = bit1 ? (bit0 ? a1[i] : s[i])  : (bit0 ? r1[i] : r0[i]);
        float ov = bit1 ? (bit0 ? s[i]  : a1[i]) : (bit0 ? r0[i] : r1[i]);
        float c = fv * cst[i] + iv * gv;
        cst[i] = c;
        hp[i] = ov * tanh_c(c);
    }
    if (jv) *(float2*)&hw[j*HSTR + (bit1*2 + bit0)*2] = hv;
}

__global__ void __launch_bounds__(NT, 2) lstm2_dual_kernel(
    const float* __restrict__ x,
    const float* __restrict__ Wih1, const float* __restrict__ bih1,
    const float* __restrict__ Whh1, const float* __restrict__ bhh1,
    const float* __restrict__ Wih2, const float* __restrict__ bih2,
    const float* __restrict__ Whh2, const float* __restrict__ bhh2,
    const float* __restrict__ fcwg, const float* __restrict__ fcbg,
    float* __restrict__ out)
{
    extern __shared__ __align__(16) float sm[];
    float* sWi  = sm + OFF_WI;
    float* sWh  = sm + OFF_WH;
    float* h1d  = sm + OFF_H1;
    float* h2d  = sm + OFF_H2;
    float* xs2  = sm + OFF_XS;
    float* sfcw = sm + OFF_FC;

    const int tid  = threadIdx.x;
    const int b0   = blockIdx.x * BT;
    const int lane = tid & 31, warp = tid >> 5;
    const int cls  = lane >> 3;                      // 0:i 1:f 2:g 3:o
    const int j    = warp * 8 + (lane & 7);          // 0..55 (51..55 pad)
    const bool jv  = (j < HH);
    const int gs   = cls*HH + (jv ? j : HH - 1);
    const int bit0 = cls & 1, bit1 = (cls >> 1) & 1;

    const float sc = (cls == 2) ? C_TNH : C_SIG;
    const float a0 = (cls == 2) ? -2.f  : 1.f;
    const float d0 = (cls == 2) ?  1.f  : 0.f;

    // Whh1 in regs (pre-scaled); Wih2/Whh2 in SMEM keyed by tid (pre-scaled)
    float W1r[HH];
#pragma unroll
    for (int k = 0; k < HH; ++k) W1r[k] = sc * Whh1[gs*HH + k];
    for (int k = 0; k < HH; ++k) {
        sWi[k*NT + tid] = sc * Wih2[gs*HH + k];
        sWh[k*NT + tid] = sc * Whh2[gs*HH + k];
    }
    const float b1 = sc * (bih1[gs] + bhh1[gs]);
    const float b2 = sc * (bih2[gs] + bhh2[gs]);
    const float w1x = sc * Wih1[gs];
    const u64 b1d  = pack2(b1, b1);
    const u64 b2d  = pack2(b2, b2);
    const u64 wi1d = pack2(w1x, w1x);

    for (int i = tid; i < 2*52*HSTR; i += NT) { h1d[i] = 0.f; h2d[i] = 0.f; }
    if (tid < HH) sfcw[tid] = fcwg[tid];
    const float fcb = fcbg[0];

    float c1s[2] = {0.f, 0.f};
    float c2s[2] = {0.f, 0.f};

    // stage x chunk 0
    for (int i = tid; i < BT*TCH; i += NT) {
        int b = i >> 6, u = i & 63;
        xs2[(u << 3) + b] = x[(size_t)(b0 + b) * TT + u];
    }
    __syncthreads();

    // prologue: cell1 at t=0 (h1(-1)=0)
    {
        u64 a1c[4];
        const ulonglong2* xr = (const ulonglong2*)&xs2[0];
        ulonglong2 x03 = xr[0], x47 = xr[1];
        a1c[0] = fma2(wi1d, x03.x, b1d);
        a1c[1] = fma2(wi1d, x03.y, b1d);
        a1c[2] = fma2(wi1d, x47.x, b1d);
        a1c[3] = fma2(wi1d, x47.y, b1d);
        gates_update8(a1c, a0, d0, bit0, bit1, c1s, h1d, j, jv);
    }
    __syncthreads();

    // ============ main loop: one barrier per timestep ============
    // invariant: h1(t) in h1d[t&1], h2(t-1) in h2d[(t+1)&1]
    for (int t = 0; t < TT; ++t) {
        // fc head for t-1 (h2d[(t-1)&1] stable this iteration)
        if (t > 0 && tid < 64) {
            const float* h2p = h2d + ((t - 1) & 1) * 52*HSTR;
            int b = tid >> 3, q = tid & 7;
            float a = 0.f;
            for (int k = q; k < HH; k += 8)
                a += h2p[k*HSTR + b] * sfcw[k];
            a += __shfl_xor_sync(0xFFFFFFFFu, a, 1);
            a += __shfl_xor_sync(0xFFFFFFFFu, a, 2);
            a += __shfl_xor_sync(0xFFFFFFFFu, a, 4);
            if (q == 0) out[(size_t)(b0 + b) * TT + (t - 1)] = a + fcb;
        }

        const int tn = t + 1;
        if ((tn & 63) == 0 && t < TT - 1) {
            __syncthreads();
            for (int i = tid; i < BT*TCH; i += NT) {
                int b = i >> 6, u = i & 63;
                xs2[(u << 3) + b] = x[(size_t)(b0 + b) * TT + tn + u];
            }
            __syncthreads();
        }
        const int tc = tn & 63;   // stale at t=511; result discarded

        const float* h1cur = h1d + (t & 1) * 52*HSTR;
        const float* h2prv = h2d + ((t + 1) & 1) * 52*HSTR;
        float*       h1nxt = h1d + ((t + 1) & 1) * 52*HSTR;
        float*       h2cur = h2d + (t & 1) * 52*HSTR;

        u64 a1c[4], a2c[4];
        {
            const ulonglong2* xr = (const ulonglong2*)&xs2[tc << 3];
            ulonglong2 x03 = xr[0], x47 = xr[1];
            a1c[0] = fma2(wi1d, x03.x, b1d);
            a1c[1] = fma2(wi1d, x03.y, b1d);
            a1c[2] = fma2(wi1d, x47.x, b1d);
            a1c[3] = fma2(wi1d, x47.y, b1d);
        }
#pragma unroll
        for (int i = 0; i < 4; ++i) a2c[i] = b2d;

#pragma unroll
        for (int k = 0; k < HH; ++k) {
            float w1s = W1r[k];
            float wis = sWi[k*NT + tid];
            float whs = sWh[k*NT + tid];
            u64 w1 = pack2(w1s, w1s);
            u64 wi = pack2(wis, wis);
            u64 wh = pack2(whs, whs);
            ulonglong2 pA = *(const ulonglong2*)&h1cur[k*HSTR];
            ulonglong2 pB = *(const ulonglong2*)&h1cur[k*HSTR + 4];
            ulonglong2 qA = *(const ulonglong2*)&h2prv[k*HSTR];
            ulonglong2 qB = *(const ulonglong2*)&h2prv[k*HSTR + 4];
            a1c[0] = fma2(w1, pA.x, a1c[0]);
            a1c[1] = fma2(w1, pA.y, a1c[1]);
            a1c[2] = fma2(w1, pB.x, a1c[2]);
            a1c[3] = fma2(w1, pB.y, a1c[3]);
            a2c[0] = fma2(wi, pA.x, a2c[0]);
            a2c[1] = fma2(wi, pA.y, a2c[1]);
            a2c[2] = fma2(wi, pB.x, a2c[2]);
            a2c[3] = fma2(wi, pB.y, a2c[3]);
            a2c[0] = fma2(wh, qA.x, a2c[0]);
            a2c[1] = fma2(wh, qA.y, a2c[1]);
            a2c[2] = fma2(wh, qB.x, a2c[2]);
            a2c[3] = fma2(wh, qB.y, a2c[3]);
        }

        gates_update8(a2c, a0, d0, bit0, bit1, c2s, h2cur, j, jv);
        gates_update8(a1c, a0, d0, bit0, bit1, c1s, h1nxt, j, jv);

        __syncthreads();
    }

    // final fc for t = 511
    if (tid < 64) {
        const float* h2p = h2d + ((TT - 1) & 1) * 52*HSTR;
        int b = tid >> 3, q = tid & 7;
        float a = 0.f;
        for (int k = q; k < HH; k += 8)
            a += h2p[k*HSTR + b] * sfcw[k];
        a += __shfl_xor_sync(0xFFFFFFFFu, a, 1);
        a += __shfl_xor_sync(0xFFFFFFFFu, a, 2);
        a += __shfl_xor_sync(0xFFFFFFFFu, a, 4);
        if (q == 0) out[(size_t)(b0 + b) * TT + (TT - 1)] = a + fcb;
    }
}

extern "C" void kernel_launch(void* const* d_in, const int* in_sizes, int n_in,
                              void* d_out, int out_size)
{
    const float* x    = (const float*)d_in[0];
    // d_in[1] = future (0) — ignored
    const float* Wih1 = (const float*)d_in[2];
    const float* bih1 = (const float*)d_in[3];
    const float* Whh1 = (const float*)d_in[4];
    const float* bhh1 = (const float*)d_in[5];
    const float* Wih2 = (const float*)d_in[6];
    const float* bih2 = (const float*)d_in[7];
    const float* Whh2 = (const float*)d_in[8];
    const float* bhh2 = (const float*)d_in[9];
    const float* fcw  = (const float*)d_in[10];
    const float* fcb  = (const float*)d_in[11];
    float* out = (float*)d_out;

    const size_t smem = SMF * sizeof(float);   // ~101 KB -> two CTAs co-resident
    cudaFuncSetAttribute(lstm2_dual_kernel,
                         cudaFuncAttributeMaxDynamicSharedMemorySize, (int)smem);

    lstm2_dual_kernel<<<GRID, NT, smem>>>(
        x, Wih1, bih1, Whh1, bhh1, Wih2, bih2, Whh2, bhh2, fcw, fcb, out);
}